// round 13
// baseline (speedup 1.0000x reference)
#include <cuda_runtime.h>
#include <cuda_bf16.h>

#define THR_LO 0.6f
#define THR_HI 0.8f

#define GRID_BLOCKS 592    // 148 SMs * 4 resident = ONE full wave
#define BLOCK_THREADS 256
#define NWARPS 8
#define RING 64            // per-warp masked-edge ring (power of 2)

// Accumulators + work-stealing counters. Zero at module load; the LAST
// block of each launch resets everything => every graph replay starts clean.
__device__ double g_acc[4];
__device__ int g_done;
__device__ int g_tilec[4];   // per-quarter tile counters (contention / 4)

__global__ void __launch_bounds__(BLOCK_THREADS, 4)
lp_fused_kernel(const void* __restrict__ edges,
                const float* __restrict__ probas,
                const float* __restrict__ feats,
                float* __restrict__ out,
                int n_edges, int n_nodes, int qchunk, int nblocks) {
    __shared__ int2 s_buf[NWARPS][RING];
    __shared__ int s_is64;
    __shared__ float s_red[4][NWARPS];
    __shared__ int s_last;

    int tid = threadIdx.x;
    int lane = tid & 31;
    int w = tid >> 5;
    int g = lane >> 3;        // dense phase: group 0..3 (one edge each)
    int q = lane & 7;         // float4 chunk index within group

    if (tid == 0) {
        // int64 edges: odd 32-bit words (high halves of idx < 2^31) are zero.
        const int4* hw = reinterpret_cast<const int4*>(edges);
        int4 a = __ldg(&hw[0]);
        int4 b = __ldg(&hw[1]);
        s_is64 = ((a.y | a.w | b.y | b.w) == 0) ? 1 : 0;
    }
    __syncthreads();
    const int is64 = s_is64;

    const longlong2* e64 = reinterpret_cast<const longlong2*>(edges);
    const int2* e32 = reinterpret_cast<const int2*>(edges);
    const char* fbase = reinterpret_cast<const char*>(feats);
    // Row i starts at byte i << 8 (64 floats * 4B = 256B per row).
    const unsigned qoff1 = (unsigned)q * 16u;        // bytes 0..112
    const unsigned qoff2 = qoff1 + 128u;             // bytes 128..240

    // Work stealing: this warp serves quarter (w & 3).
    int quarter = w & 3;
    int qbeg = quarter * qchunk;
    int qend = min(qbeg + qchunk, n_edges);
    int ntiles = (qend - qbeg + 127) >> 7;           // 128-edge tiles

    float n_sim = 0.f, n_dis = 0.f, s_sim = 0.f, s_dis = 0.f;
    int wcnt = 0;   // unprocessed ring entries (warp-uniform)
    int head = 0;   // ring read position (warp-uniform)

    auto ld4 = [&](unsigned byte_off) {
        return __ldg(reinterpret_cast<const float4*>(fbase + byte_off));
    };

    // Dense-process 32 buffered masked edges: pairs of 4-edge passes with all
    // 8 LDG.128 issued before any FMA; two shfl chains interleaved.
    auto flush32 = [&]() {
        __syncwarp();
#pragma unroll
        for (int t = 0; t < 8; t += 2) {
            int2 e0 = s_buf[w][(head + t * 4 + g) & (RING - 1)];
            int2 e1 = s_buf[w][(head + (t + 1) * 4 + g) & (RING - 1)];
            unsigned o0i = (unsigned)(e0.x & 0x7FFFFFFF) << 8;
            unsigned o0j = (unsigned)e0.y << 8;
            unsigned o1i = (unsigned)(e1.x & 0x7FFFFFFF) << 8;
            unsigned o1j = (unsigned)e1.y << 8;
            float4 a0 = ld4(o0i + qoff1);
            float4 c0 = ld4(o0i + qoff2);
            float4 b0 = ld4(o0j + qoff1);
            float4 d0 = ld4(o0j + qoff2);
            float4 a1 = ld4(o1i + qoff1);
            float4 c1 = ld4(o1i + qoff2);
            float4 b1 = ld4(o1j + qoff1);
            float4 d1 = ld4(o1j + qoff2);

            float x, y, z, v;
            x = a0.x - b0.x; y = a0.y - b0.y; z = a0.z - b0.z; v = a0.w - b0.w;
            float s0 = fmaf(x, x, fmaf(y, y, fmaf(z, z, v * v)));
            x = c0.x - d0.x; y = c0.y - d0.y; z = c0.z - d0.z; v = c0.w - d0.w;
            s0 += fmaf(x, x, fmaf(y, y, fmaf(z, z, v * v)));
            x = a1.x - b1.x; y = a1.y - b1.y; z = a1.z - b1.z; v = a1.w - b1.w;
            float s1 = fmaf(x, x, fmaf(y, y, fmaf(z, z, v * v)));
            x = c1.x - d1.x; y = c1.y - d1.y; z = c1.z - d1.z; v = c1.w - d1.w;
            s1 += fmaf(x, x, fmaf(y, y, fmaf(z, z, v * v)));

            s0 += __shfl_xor_sync(0xFFFFFFFFu, s0, 1);
            s1 += __shfl_xor_sync(0xFFFFFFFFu, s1, 1);
            s0 += __shfl_xor_sync(0xFFFFFFFFu, s0, 2);
            s1 += __shfl_xor_sync(0xFFFFFFFFu, s1, 2);
            s0 += __shfl_xor_sync(0xFFFFFFFFu, s0, 4);
            s1 += __shfl_xor_sync(0xFFFFFFFFu, s1, 4);

            if (q == 0) {
                float d = sqrtf(s0);
                if (e0.x < 0) s_sim += fminf(d, 100.f);
                else          s_dis += -fmaxf(log1pf(-expf(-d)), -100.f);
                d = sqrtf(s1);
                if (e1.x < 0) s_sim += fminf(d, 100.f);
                else          s_dis += -fmaxf(log1pf(-expf(-d)), -100.f);
            }
        }
        head = (head + 32) & (RING - 1);
        wcnt -= 32;
    };

    // ---- Stealing loop: grab 128-edge tiles; next grab prefetched so the
    // ATOMG latency hides behind the current tile's processing. All state
    // (tile index) is warp-uniform via shfl.
    int my = 0;
    if (lane == 0) my = atomicAdd(&g_tilec[quarter], 1);
    my = __shfl_sync(0xFFFFFFFFu, my, 0);

    while (my < ntiles) {
        int nxt = 0;
        if (lane == 0) nxt = atomicAdd(&g_tilec[quarter], 1);
        nxt = __shfl_sync(0xFFFFFFFFu, nxt, 0);

        int mb = qbeg + (my << 7);                 // 128-edge macro-tile
        int ei[4], ej[4];
        bool val[4];
#pragma unroll
        for (int t = 0; t < 4; t++) {
            int e = mb + t * 32 + lane;
            val[t] = e < qend;
            int i = 0, j = 0;
            if (val[t]) {
                if (is64) { longlong2 ij = e64[e]; i = (int)ij.x; j = (int)ij.y; }
                else      { int2 ij = e32[e];      i = ij.x;      j = ij.y; }
            }
            if ((unsigned)i >= (unsigned)n_nodes ||
                (unsigned)j >= (unsigned)n_nodes) val[t] = false;
            ei[t] = val[t] ? i : 0;
            ej[t] = val[t] ? j : 0;
        }
        float pi[4], pj[4];
#pragma unroll
        for (int t = 0; t < 4; t++) {
            pi[t] = __ldg(&probas[ei[t]]);
            pj[t] = __ldg(&probas[ej[t]]);
        }
#pragma unroll
        for (int t = 0; t < 4; t++) {
            bool ms = false, md = false;
            if (val[t]) {
                ms = (pi[t] >= THR_HI) && (pj[t] >= THR_HI);
                md = ((pi[t] >= THR_HI) && (pj[t] < THR_LO)) ||
                     ((pj[t] >= THR_HI) && (pi[t] < THR_LO));
            }
            n_sim += ms ? 1.f : 0.f;
            n_dis += md ? 1.f : 0.f;

            unsigned bal = __ballot_sync(0xFFFFFFFFu, ms | md);
            int rank = __popc(bal & ((1u << lane) - 1u));
            if (ms | md)
                s_buf[w][(head + wcnt + rank) & (RING - 1)] =
                    make_int2(ei[t] | (ms ? (int)0x80000000 : 0), ej[t]);
            wcnt += __popc(bal);                  // warp-uniform
            if (wcnt >= 32) flush32();            // warp-uniform condition
        }

        my = nxt;
    }

    // Tail (< 32 entries): warp-uniform bound, predicated work, all lanes
    // run the shfls (R4 lesson).
    if (wcnt > 0) {
        __syncwarp();
        for (int t = 0; t < wcnt; t += 4) {
            int it = t + g;
            bool act = it < wcnt;
            int2 ed = act ? s_buf[w][(head + it) & (RING - 1)]
                          : make_int2(0, 0);
            bool ms = ed.x < 0;
            unsigned oi = (unsigned)(ed.x & 0x7FFFFFFF) << 8;
            unsigned oj = (unsigned)ed.y << 8;
            float4 a1 = make_float4(0.f, 0.f, 0.f, 0.f);
            float4 a2 = a1, b1 = a1, b2 = a1;
            if (act) {
                a1 = ld4(oi + qoff1);  a2 = ld4(oi + qoff2);
                b1 = ld4(oj + qoff1);  b2 = ld4(oj + qoff2);
            }
            float dx = a1.x - b1.x, dy = a1.y - b1.y;
            float dz = a1.z - b1.z, dw = a1.w - b1.w;
            float s = fmaf(dx, dx, fmaf(dy, dy, fmaf(dz, dz, dw * dw)));
            dx = a2.x - b2.x; dy = a2.y - b2.y;
            dz = a2.z - b2.z; dw = a2.w - b2.w;
            s += fmaf(dx, dx, fmaf(dy, dy, fmaf(dz, dz, dw * dw)));
            s += __shfl_xor_sync(0xFFFFFFFFu, s, 1);
            s += __shfl_xor_sync(0xFFFFFFFFu, s, 2);
            s += __shfl_xor_sync(0xFFFFFFFFu, s, 4);
            if (act && q == 0) {
                float d = sqrtf(s);
                if (ms) s_sim += fminf(d, 100.f);
                else    s_dis += -fmaxf(log1pf(-expf(-d)), -100.f);
            }
        }
    }

    // Block reduce 4 partials
#pragma unroll
    for (int off = 16; off > 0; off >>= 1) {
        n_sim += __shfl_down_sync(0xFFFFFFFFu, n_sim, off);
        n_dis += __shfl_down_sync(0xFFFFFFFFu, n_dis, off);
        s_sim += __shfl_down_sync(0xFFFFFFFFu, s_sim, off);
        s_dis += __shfl_down_sync(0xFFFFFFFFu, s_dis, off);
    }
    if (lane == 0) {
        s_red[0][w] = n_sim; s_red[1][w] = n_dis;
        s_red[2][w] = s_sim; s_red[3][w] = s_dis;
    }
    __syncthreads();

    if (tid == 0) {
        float a0 = 0.f, a1 = 0.f, a2 = 0.f, a3 = 0.f;
#pragma unroll
        for (int k = 0; k < NWARPS; k++) {
            a0 += s_red[0][k]; a1 += s_red[1][k];
            a2 += s_red[2][k]; a3 += s_red[3][k];
        }
        atomicAdd(&g_acc[0], (double)a0);
        atomicAdd(&g_acc[1], (double)a1);
        atomicAdd(&g_acc[2], (double)a2);
        atomicAdd(&g_acc[3], (double)a3);
        __threadfence();
        int ticket = atomicAdd(&g_done, 1);
        s_last = (ticket == nblocks - 1);
    }
    __syncthreads();

    // Last block computes the loss, then resets ALL state for the replay.
    if (s_last && tid == 0) {
        double ns = g_acc[0], nd = g_acc[1], ss = g_acc[2], ds = g_acc[3];
        double total = ns + nd;
        double loss = (ss * (nd / total) + ds * (ns / total)) / total;
        out[0] = (float)loss;
        g_acc[0] = 0.0; g_acc[1] = 0.0; g_acc[2] = 0.0; g_acc[3] = 0.0;
        g_done = 0;
        g_tilec[0] = 0; g_tilec[1] = 0; g_tilec[2] = 0; g_tilec[3] = 0;
    }
}

extern "C" void kernel_launch(void* const* d_in, const int* in_sizes, int n_in,
                              void* d_out, int out_size) {
    // Identify inputs by element count (robust to metadata ordering):
    //   probas: n_nodes (smallest), feats: n_nodes*64, edges: the rest.
    int idx_e = 0, idx_p = 1, idx_f = 2;
    if (n_in == 3) {
        int smallest = 0;
        for (int k = 1; k < 3; k++)
            if (in_sizes[k] < in_sizes[smallest]) smallest = k;
        int pf = -1, ee = -1;
        for (int k = 0; k < 3; k++) {
            if (k == smallest) continue;
            if (in_sizes[k] == in_sizes[smallest] * 64) pf = k;
            else ee = k;
        }
        if (pf >= 0 && ee >= 0) { idx_p = smallest; idx_f = pf; idx_e = ee; }
    }

    const void* edges = d_in[idx_e];
    const float* probas = (const float*)d_in[idx_p];
    const float* feats = (const float*)d_in[idx_f];
    float* out = (float*)d_out;

    int n_edges = in_sizes[idx_e] / 2;
    int n_nodes = in_sizes[idx_p];
    int qchunk = (n_edges + 3) / 4;   // quarter size for stealing counters

    lp_fused_kernel<<<GRID_BLOCKS, BLOCK_THREADS>>>(
        edges, probas, feats, out, n_edges, n_nodes, qchunk, GRID_BLOCKS);
}

// round 14
// speedup vs baseline: 1.1402x; 1.1402x over previous
#include <cuda_runtime.h>
#include <cuda_bf16.h>

#define THR_LO 0.6f
#define THR_HI 0.8f

#define GRID_BLOCKS 1184   // 148 SMs * 8 CTAs of 128 thr = ONE full wave
#define BLOCK_THREADS 128
#define NWARPS 4
#define RING 64            // per-warp masked-edge ring (power of 2)

// Accumulators: n_sim, n_disim, sim_sum, disim_sum (+ finish ticket).
// Zero at module load; the LAST block of each launch resets them after
// computing the loss, so every graph replay starts from zero.
__device__ double g_acc[4];
__device__ int g_done;

__global__ void __launch_bounds__(BLOCK_THREADS, 8)
lp_fused_kernel(const void* __restrict__ edges,
                const float* __restrict__ probas,
                const float* __restrict__ feats,
                float* __restrict__ out,
                int n_edges, int n_nodes, int chunk, int nblocks) {
    __shared__ int2 s_buf[NWARPS][RING];
    __shared__ int s_is64;
    __shared__ float s_red[4][NWARPS];
    __shared__ int s_last;

    int tid = threadIdx.x;
    int lane = tid & 31;
    int w = tid >> 5;
    int g = lane >> 3;        // dense phase: group 0..3 (one edge each)
    int q = lane & 7;         // float4 chunk index within group

    if (tid == 0) {
        // int64 edges: odd 32-bit words (high halves of idx < 2^31) are zero.
        const int4* hw = reinterpret_cast<const int4*>(edges);
        int4 a = __ldg(&hw[0]);
        int4 b = __ldg(&hw[1]);
        s_is64 = ((a.y | a.w | b.y | b.w) == 0) ? 1 : 0;
    }
    __syncthreads();
    const int is64 = s_is64;

    const longlong2* e64 = reinterpret_cast<const longlong2*>(edges);
    const int2* e32 = reinterpret_cast<const int2*>(edges);
    const char* fbase = reinterpret_cast<const char*>(feats);
    // Row i starts at byte i << 8 (64 floats * 4B = 256B per row).
    const unsigned qoff1 = (unsigned)q * 16u;        // bytes 0..112
    const unsigned qoff2 = qoff1 + 128u;             // bytes 128..240

    // Per-warp contiguous range: 4 batched sub-tiles of 32 per macro-iter.
    int beg = blockIdx.x * chunk;
    int end = min(beg + chunk, n_edges);
    int ws = (chunk + NWARPS - 1) / NWARPS;
    int wbeg = beg + w * ws;
    int wend = min(wbeg + ws, end);

    int cnt_sim = 0, cnt_dis = 0;       // exact integer counts
    float s_sim = 0.f, s_dis = 0.f;
    int wcnt = 0;   // unprocessed ring entries (warp-uniform)
    int head = 0;   // ring read position (warp-uniform)

    auto ld4 = [&](unsigned byte_off) {
        return __ldg(reinterpret_cast<const float4*>(fbase + byte_off));
    };

    // Dense-process 32 buffered masked edges: pairs of 4-edge passes with all
    // 8 LDG.128 issued before any FMA; two shfl chains interleaved.
    auto flush32 = [&]() {
        __syncwarp();
#pragma unroll
        for (int t = 0; t < 8; t += 2) {
            int2 e0 = s_buf[w][(head + t * 4 + g) & (RING - 1)];
            int2 e1 = s_buf[w][(head + (t + 1) * 4 + g) & (RING - 1)];
            unsigned o0i = (unsigned)(e0.x & 0x7FFFFFFF) << 8;
            unsigned o0j = (unsigned)e0.y << 8;
            unsigned o1i = (unsigned)(e1.x & 0x7FFFFFFF) << 8;
            unsigned o1j = (unsigned)e1.y << 8;
            float4 a0 = ld4(o0i + qoff1);
            float4 c0 = ld4(o0i + qoff2);
            float4 b0 = ld4(o0j + qoff1);
            float4 d0 = ld4(o0j + qoff2);
            float4 a1 = ld4(o1i + qoff1);
            float4 c1 = ld4(o1i + qoff2);
            float4 b1 = ld4(o1j + qoff1);
            float4 d1 = ld4(o1j + qoff2);

            float x, y, z, v;
            x = a0.x - b0.x; y = a0.y - b0.y; z = a0.z - b0.z; v = a0.w - b0.w;
            float s0 = fmaf(x, x, fmaf(y, y, fmaf(z, z, v * v)));
            x = c0.x - d0.x; y = c0.y - d0.y; z = c0.z - d0.z; v = c0.w - d0.w;
            s0 += fmaf(x, x, fmaf(y, y, fmaf(z, z, v * v)));
            x = a1.x - b1.x; y = a1.y - b1.y; z = a1.z - b1.z; v = a1.w - b1.w;
            float s1 = fmaf(x, x, fmaf(y, y, fmaf(z, z, v * v)));
            x = c1.x - d1.x; y = c1.y - d1.y; z = c1.z - d1.z; v = c1.w - d1.w;
            s1 += fmaf(x, x, fmaf(y, y, fmaf(z, z, v * v)));

            s0 += __shfl_xor_sync(0xFFFFFFFFu, s0, 1);
            s1 += __shfl_xor_sync(0xFFFFFFFFu, s1, 1);
            s0 += __shfl_xor_sync(0xFFFFFFFFu, s0, 2);
            s1 += __shfl_xor_sync(0xFFFFFFFFu, s1, 2);
            s0 += __shfl_xor_sync(0xFFFFFFFFu, s0, 4);
            s1 += __shfl_xor_sync(0xFFFFFFFFu, s1, 4);

            if (q == 0) {
                float d = sqrtf(s0);
                if (e0.x < 0) s_sim += fminf(d, 100.f);
                else          s_dis += -fmaxf(log1pf(-expf(-d)), -100.f);
                d = sqrtf(s1);
                if (e1.x < 0) s_sim += fminf(d, 100.f);
                else          s_dis += -fmaxf(log1pf(-expf(-d)), -100.f);
            }
        }
        head = (head + 32) & (RING - 1);
        wcnt -= 32;
    };

    // Scan: 128 edges per warp-iter, all loads batched for MLP.
    for (int mb = wbeg; mb < wend; mb += 128) {   // warp-uniform bound
        int ei[4], ej[4];
        bool val[4];
#pragma unroll
        for (int t = 0; t < 4; t++) {
            int e = mb + t * 32 + lane;
            val[t] = e < wend;
            int i = 0, j = 0;
            if (val[t]) {
                if (is64) { longlong2 ij = e64[e]; i = (int)ij.x; j = (int)ij.y; }
                else      { int2 ij = e32[e];      i = ij.x;      j = ij.y; }
            }
            if ((unsigned)i >= (unsigned)n_nodes ||
                (unsigned)j >= (unsigned)n_nodes) val[t] = false;
            ei[t] = val[t] ? i : 0;
            ej[t] = val[t] ? j : 0;
        }
        float pi[4], pj[4];
#pragma unroll
        for (int t = 0; t < 4; t++) {
            pi[t] = __ldg(&probas[ei[t]]);
            pj[t] = __ldg(&probas[ej[t]]);
        }
#pragma unroll
        for (int t = 0; t < 4; t++) {
            bool ms = false, md = false;
            if (val[t]) {
                ms = (pi[t] >= THR_HI) && (pj[t] >= THR_HI);
                md = ((pi[t] >= THR_HI) && (pj[t] < THR_LO)) ||
                     ((pj[t] >= THR_HI) && (pi[t] < THR_LO));
            }
            cnt_sim += ms ? 1 : 0;
            cnt_dis += md ? 1 : 0;

            unsigned bal = __ballot_sync(0xFFFFFFFFu, ms | md);
            int rank = __popc(bal & ((1u << lane) - 1u));
            if (ms | md)
                s_buf[w][(head + wcnt + rank) & (RING - 1)] =
                    make_int2(ei[t] | (ms ? (int)0x80000000 : 0), ej[t]);
            wcnt += __popc(bal);                  // warp-uniform
            if (wcnt >= 32) flush32();            // warp-uniform condition
        }
    }

    // Tail (< 32 entries): warp-uniform bound, predicated work, all lanes
    // run the shfls (R4 lesson).
    if (wcnt > 0) {
        __syncwarp();
        for (int t = 0; t < wcnt; t += 4) {
            int it = t + g;
            bool act = it < wcnt;
            int2 ed = act ? s_buf[w][(head + it) & (RING - 1)]
                          : make_int2(0, 0);
            bool ms = ed.x < 0;
            unsigned oi = (unsigned)(ed.x & 0x7FFFFFFF) << 8;
            unsigned oj = (unsigned)ed.y << 8;
            float4 a1 = make_float4(0.f, 0.f, 0.f, 0.f);
            float4 a2 = a1, b1 = a1, b2 = a1;
            if (act) {
                a1 = ld4(oi + qoff1);  a2 = ld4(oi + qoff2);
                b1 = ld4(oj + qoff1);  b2 = ld4(oj + qoff2);
            }
            float dx = a1.x - b1.x, dy = a1.y - b1.y;
            float dz = a1.z - b1.z, dw = a1.w - b1.w;
            float s = fmaf(dx, dx, fmaf(dy, dy, fmaf(dz, dz, dw * dw)));
            dx = a2.x - b2.x; dy = a2.y - b2.y;
            dz = a2.z - b2.z; dw = a2.w - b2.w;
            s += fmaf(dx, dx, fmaf(dy, dy, fmaf(dz, dz, dw * dw)));
            s += __shfl_xor_sync(0xFFFFFFFFu, s, 1);
            s += __shfl_xor_sync(0xFFFFFFFFu, s, 2);
            s += __shfl_xor_sync(0xFFFFFFFFu, s, 4);
            if (act && q == 0) {
                float d = sqrtf(s);
                if (ms) s_sim += fminf(d, 100.f);
                else    s_dis += -fmaxf(log1pf(-expf(-d)), -100.f);
            }
        }
    }

    // Block reduce 4 partials (counts as float after warp totals)
    float n_sim = (float)cnt_sim, n_dis = (float)cnt_dis;
#pragma unroll
    for (int off = 16; off > 0; off >>= 1) {
        n_sim += __shfl_down_sync(0xFFFFFFFFu, n_sim, off);
        n_dis += __shfl_down_sync(0xFFFFFFFFu, n_dis, off);
        s_sim += __shfl_down_sync(0xFFFFFFFFu, s_sim, off);
        s_dis += __shfl_down_sync(0xFFFFFFFFu, s_dis, off);
    }
    if (lane == 0) {
        s_red[0][w] = n_sim; s_red[1][w] = n_dis;
        s_red[2][w] = s_sim; s_red[3][w] = s_dis;
    }
    __syncthreads();

    if (tid == 0) {
        float a0 = 0.f, a1 = 0.f, a2 = 0.f, a3 = 0.f;
#pragma unroll
        for (int k = 0; k < NWARPS; k++) {
            a0 += s_red[0][k]; a1 += s_red[1][k];
            a2 += s_red[2][k]; a3 += s_red[3][k];
        }
        atomicAdd(&g_acc[0], (double)a0);
        atomicAdd(&g_acc[1], (double)a1);
        atomicAdd(&g_acc[2], (double)a2);
        atomicAdd(&g_acc[3], (double)a3);
        __threadfence();
        int ticket = atomicAdd(&g_done, 1);
        s_last = (ticket == nblocks - 1);
    }
    __syncthreads();

    // Last block computes the loss, then resets state for the next replay.
    if (s_last && tid == 0) {
        double ns = g_acc[0], nd = g_acc[1], ss = g_acc[2], ds = g_acc[3];
        double total = ns + nd;
        double loss = (ss * (nd / total) + ds * (ns / total)) / total;
        out[0] = (float)loss;
        g_acc[0] = 0.0; g_acc[1] = 0.0; g_acc[2] = 0.0; g_acc[3] = 0.0;
        g_done = 0;
    }
}

extern "C" void kernel_launch(void* const* d_in, const int* in_sizes, int n_in,
                              void* d_out, int out_size) {
    // Identify inputs by element count (robust to metadata ordering):
    //   probas: n_nodes (smallest), feats: n_nodes*64, edges: the rest.
    int idx_e = 0, idx_p = 1, idx_f = 2;
    if (n_in == 3) {
        int smallest = 0;
        for (int k = 1; k < 3; k++)
            if (in_sizes[k] < in_sizes[smallest]) smallest = k;
        int pf = -1, ee = -1;
        for (int k = 0; k < 3; k++) {
            if (k == smallest) continue;
            if (in_sizes[k] == in_sizes[smallest] * 64) pf = k;
            else ee = k;
        }
        if (pf >= 0 && ee >= 0) { idx_p = smallest; idx_f = pf; idx_e = ee; }
    }

    const void* edges = d_in[idx_e];
    const float* probas = (const float*)d_in[idx_p];
    const float* feats = (const float*)d_in[idx_f];
    float* out = (float*)d_out;

    int n_edges = in_sizes[idx_e] / 2;
    int n_nodes = in_sizes[idx_p];
    int chunk = (n_edges + GRID_BLOCKS - 1) / GRID_BLOCKS;

    lp_fused_kernel<<<GRID_BLOCKS, BLOCK_THREADS>>>(
        edges, probas, feats, out, n_edges, n_nodes, chunk, GRID_BLOCKS);
}

// round 15
// speedup vs baseline: 1.1509x; 1.0094x over previous
#include <cuda_runtime.h>
#include <cuda_bf16.h>

#define THR_LO 0.6f
#define THR_HI 0.8f

#define GRID_BLOCKS 740    // 148 SMs * 5 resident (51 regs) = ONE full wave
#define BLOCK_THREADS 256
#define NWARPS 8
#define RING 64            // per-warp masked-edge ring (power of 2)

// Accumulators: n_sim, n_disim, sim_sum, disim_sum  (+ finish ticket).
// Zero at module load; the LAST block of each launch resets them after
// computing the loss, so every graph replay starts from zero.
__device__ double g_acc[4];
__device__ int g_done;

__global__ void __launch_bounds__(BLOCK_THREADS, 5)
lp_fused_kernel(const void* __restrict__ edges,
                const float* __restrict__ probas,
                const float* __restrict__ feats,
                float* __restrict__ out,
                int n_edges, int n_nodes, int chunk, int nblocks) {
    __shared__ int2 s_buf[NWARPS][RING];
    __shared__ int s_is64;
    __shared__ float s_red[4][NWARPS];
    __shared__ int s_last;

    int tid = threadIdx.x;
    int lane = tid & 31;
    int w = tid >> 5;
    int g = lane >> 3;        // dense phase: group 0..3 (one edge each)
    int q = lane & 7;         // float4 chunk index within group

    if (tid == 0) {
        // int64 edges: odd 32-bit words (high halves of idx < 2^31) are zero.
        const int4* hw = reinterpret_cast<const int4*>(edges);
        int4 a = __ldg(&hw[0]);
        int4 b = __ldg(&hw[1]);
        s_is64 = ((a.y | a.w | b.y | b.w) == 0) ? 1 : 0;
    }
    __syncthreads();
    const int is64 = s_is64;

    const longlong2* e64 = reinterpret_cast<const longlong2*>(edges);
    const int2* e32 = reinterpret_cast<const int2*>(edges);
    const char* fbase = reinterpret_cast<const char*>(feats);
    // Row i starts at byte i << 8 (64 floats * 4B = 256B per row).
    const unsigned qoff1 = (unsigned)q * 16u;        // bytes 0..112
    const unsigned qoff2 = qoff1 + 128u;             // bytes 128..240

    // Per-warp contiguous range: 4 batched sub-tiles of 32 per macro-iter.
    int beg = blockIdx.x * chunk;
    int end = min(beg + chunk, n_edges);
    int ws = (chunk + NWARPS - 1) / NWARPS;
    int wbeg = beg + w * ws;
    int wend = min(wbeg + ws, end);

    float n_sim = 0.f, n_dis = 0.f, s_sim = 0.f, s_dis = 0.f;
    int wcnt = 0;   // unprocessed ring entries (warp-uniform)
    int head = 0;   // ring read position (warp-uniform)

    auto ld4 = [&](unsigned byte_off) {
        return __ldg(reinterpret_cast<const float4*>(fbase + byte_off));
    };

    // Dense-process 32 buffered masked edges: pairs of 4-edge passes with all
    // 8 LDG.128 issued before any FMA; two shfl chains interleaved.
    auto flush32 = [&]() {
        __syncwarp();
#pragma unroll
        for (int t = 0; t < 8; t += 2) {
            int2 e0 = s_buf[w][(head + t * 4 + g) & (RING - 1)];
            int2 e1 = s_buf[w][(head + (t + 1) * 4 + g) & (RING - 1)];
            unsigned o0i = (unsigned)(e0.x & 0x7FFFFFFF) << 8;
            unsigned o0j = (unsigned)e0.y << 8;
            unsigned o1i = (unsigned)(e1.x & 0x7FFFFFFF) << 8;
            unsigned o1j = (unsigned)e1.y << 8;
            float4 a0 = ld4(o0i + qoff1);
            float4 c0 = ld4(o0i + qoff2);
            float4 b0 = ld4(o0j + qoff1);
            float4 d0 = ld4(o0j + qoff2);
            float4 a1 = ld4(o1i + qoff1);
            float4 c1 = ld4(o1i + qoff2);
            float4 b1 = ld4(o1j + qoff1);
            float4 d1 = ld4(o1j + qoff2);

            float x, y, z, v;
            x = a0.x - b0.x; y = a0.y - b0.y; z = a0.z - b0.z; v = a0.w - b0.w;
            float s0 = fmaf(x, x, fmaf(y, y, fmaf(z, z, v * v)));
            x = c0.x - d0.x; y = c0.y - d0.y; z = c0.z - d0.z; v = c0.w - d0.w;
            s0 += fmaf(x, x, fmaf(y, y, fmaf(z, z, v * v)));
            x = a1.x - b1.x; y = a1.y - b1.y; z = a1.z - b1.z; v = a1.w - b1.w;
            float s1 = fmaf(x, x, fmaf(y, y, fmaf(z, z, v * v)));
            x = c1.x - d1.x; y = c1.y - d1.y; z = c1.z - d1.z; v = c1.w - d1.w;
            s1 += fmaf(x, x, fmaf(y, y, fmaf(z, z, v * v)));

            s0 += __shfl_xor_sync(0xFFFFFFFFu, s0, 1);
            s1 += __shfl_xor_sync(0xFFFFFFFFu, s1, 1);
            s0 += __shfl_xor_sync(0xFFFFFFFFu, s0, 2);
            s1 += __shfl_xor_sync(0xFFFFFFFFu, s1, 2);
            s0 += __shfl_xor_sync(0xFFFFFFFFu, s0, 4);
            s1 += __shfl_xor_sync(0xFFFFFFFFu, s1, 4);

            if (q == 0) {
                float d = sqrtf(s0);
                if (e0.x < 0) s_sim += fminf(d, 100.f);
                else          s_dis += -fmaxf(log1pf(-expf(-d)), -100.f);
                d = sqrtf(s1);
                if (e1.x < 0) s_sim += fminf(d, 100.f);
                else          s_dis += -fmaxf(log1pf(-expf(-d)), -100.f);
            }
        }
        head = (head + 32) & (RING - 1);
        wcnt -= 32;
    };

    // Scan: 128 edges per warp-iter, all loads batched for MLP.
    for (int mb = wbeg; mb < wend; mb += 128) {   // warp-uniform bound
        int ei[4], ej[4];
        bool val[4];
#pragma unroll
        for (int t = 0; t < 4; t++) {
            int e = mb + t * 32 + lane;
            val[t] = e < wend;
            int i = 0, j = 0;
            if (val[t]) {
                if (is64) { longlong2 ij = e64[e]; i = (int)ij.x; j = (int)ij.y; }
                else      { int2 ij = e32[e];      i = ij.x;      j = ij.y; }
            }
            if ((unsigned)i >= (unsigned)n_nodes ||
                (unsigned)j >= (unsigned)n_nodes) val[t] = false;
            ei[t] = val[t] ? i : 0;
            ej[t] = val[t] ? j : 0;
        }
        float pi[4], pj[4];
#pragma unroll
        for (int t = 0; t < 4; t++) {
            pi[t] = __ldg(&probas[ei[t]]);
            pj[t] = __ldg(&probas[ej[t]]);
        }
#pragma unroll
        for (int t = 0; t < 4; t++) {
            bool ms = false, md = false;
            if (val[t]) {
                ms = (pi[t] >= THR_HI) && (pj[t] >= THR_HI);
                md = ((pi[t] >= THR_HI) && (pj[t] < THR_LO)) ||
                     ((pj[t] >= THR_HI) && (pi[t] < THR_LO));
            }
            n_sim += ms ? 1.f : 0.f;
            n_dis += md ? 1.f : 0.f;

            unsigned bal = __ballot_sync(0xFFFFFFFFu, ms | md);
            int rank = __popc(bal & ((1u << lane) - 1u));
            if (ms | md)
                s_buf[w][(head + wcnt + rank) & (RING - 1)] =
                    make_int2(ei[t] | (ms ? (int)0x80000000 : 0), ej[t]);
            wcnt += __popc(bal);                  // warp-uniform
            if (wcnt >= 32) flush32();            // warp-uniform condition
        }
    }

    // Tail (< 32 entries): warp-uniform bound, predicated work, all lanes
    // run the shfls (R4 lesson).
    if (wcnt > 0) {
        __syncwarp();
        for (int t = 0; t < wcnt; t += 4) {
            int it = t + g;
            bool act = it < wcnt;
            int2 ed = act ? s_buf[w][(head + it) & (RING - 1)]
                          : make_int2(0, 0);
            bool ms = ed.x < 0;
            unsigned oi = (unsigned)(ed.x & 0x7FFFFFFF) << 8;
            unsigned oj = (unsigned)ed.y << 8;
            float4 a1 = make_float4(0.f, 0.f, 0.f, 0.f);
            float4 a2 = a1, b1 = a1, b2 = a1;
            if (act) {
                a1 = ld4(oi + qoff1);  a2 = ld4(oi + qoff2);
                b1 = ld4(oj + qoff1);  b2 = ld4(oj + qoff2);
            }
            float dx = a1.x - b1.x, dy = a1.y - b1.y;
            float dz = a1.z - b1.z, dw = a1.w - b1.w;
            float s = fmaf(dx, dx, fmaf(dy, dy, fmaf(dz, dz, dw * dw)));
            dx = a2.x - b2.x; dy = a2.y - b2.y;
            dz = a2.z - b2.z; dw = a2.w - b2.w;
            s += fmaf(dx, dx, fmaf(dy, dy, fmaf(dz, dz, dw * dw)));
            s += __shfl_xor_sync(0xFFFFFFFFu, s, 1);
            s += __shfl_xor_sync(0xFFFFFFFFu, s, 2);
            s += __shfl_xor_sync(0xFFFFFFFFu, s, 4);
            if (act && q == 0) {
                float d = sqrtf(s);
                if (ms) s_sim += fminf(d, 100.f);
                else    s_dis += -fmaxf(log1pf(-expf(-d)), -100.f);
            }
        }
    }

    // Block reduce 4 partials
#pragma unroll
    for (int off = 16; off > 0; off >>= 1) {
        n_sim += __shfl_down_sync(0xFFFFFFFFu, n_sim, off);
        n_dis += __shfl_down_sync(0xFFFFFFFFu, n_dis, off);
        s_sim += __shfl_down_sync(0xFFFFFFFFu, s_sim, off);
        s_dis += __shfl_down_sync(0xFFFFFFFFu, s_dis, off);
    }
    if (lane == 0) {
        s_red[0][w] = n_sim; s_red[1][w] = n_dis;
        s_red[2][w] = s_sim; s_red[3][w] = s_dis;
    }
    __syncthreads();

    if (tid == 0) {
        float a0 = 0.f, a1 = 0.f, a2 = 0.f, a3 = 0.f;
#pragma unroll
        for (int k = 0; k < NWARPS; k++) {
            a0 += s_red[0][k]; a1 += s_red[1][k];
            a2 += s_red[2][k]; a3 += s_red[3][k];
        }
        atomicAdd(&g_acc[0], (double)a0);
        atomicAdd(&g_acc[1], (double)a1);
        atomicAdd(&g_acc[2], (double)a2);
        atomicAdd(&g_acc[3], (double)a3);
        __threadfence();
        int ticket = atomicAdd(&g_done, 1);
        s_last = (ticket == nblocks - 1);
    }
    __syncthreads();

    // Last block computes the loss, then resets state for the next replay.
    if (s_last && tid == 0) {
        double ns = g_acc[0], nd = g_acc[1], ss = g_acc[2], ds = g_acc[3];
        double total = ns + nd;
        double loss = (ss * (nd / total) + ds * (ns / total)) / total;
        out[0] = (float)loss;
        g_acc[0] = 0.0; g_acc[1] = 0.0; g_acc[2] = 0.0; g_acc[3] = 0.0;
        g_done = 0;
    }
}

extern "C" void kernel_launch(void* const* d_in, const int* in_sizes, int n_in,
                              void* d_out, int out_size) {
    // Identify inputs by element count (robust to metadata ordering):
    //   probas: n_nodes (smallest), feats: n_nodes*64, edges: the rest.
    int idx_e = 0, idx_p = 1, idx_f = 2;
    if (n_in == 3) {
        int smallest = 0;
        for (int k = 1; k < 3; k++)
            if (in_sizes[k] < in_sizes[smallest]) smallest = k;
        int pf = -1, ee = -1;
        for (int k = 0; k < 3; k++) {
            if (k == smallest) continue;
            if (in_sizes[k] == in_sizes[smallest] * 64) pf = k;
            else ee = k;
        }
        if (pf >= 0 && ee >= 0) { idx_p = smallest; idx_f = pf; idx_e = ee; }
    }

    const void* edges = d_in[idx_e];
    const float* probas = (const float*)d_in[idx_p];
    const float* feats = (const float*)d_in[idx_f];
    float* out = (float*)d_out;

    int n_edges = in_sizes[idx_e] / 2;
    int n_nodes = in_sizes[idx_p];
    int chunk = (n_edges + GRID_BLOCKS - 1) / GRID_BLOCKS;

    lp_fused_kernel<<<GRID_BLOCKS, BLOCK_THREADS>>>(
        edges, probas, feats, out, n_edges, n_nodes, chunk, GRID_BLOCKS);
}

// round 16
// speedup vs baseline: 1.2465x; 1.0830x over previous
#include <cuda_runtime.h>
#include <cuda_bf16.h>

#define THR_LO 0.6f
#define THR_HI 0.8f

#define GRID_BLOCKS 592    // 148 SMs * 4 resident (56 regs) = ONE full wave
#define BLOCK_THREADS 256
#define NWARPS 8
#define RING 64            // per-warp masked-edge ring (power of 2)

// Accumulators: n_sim, n_disim, sim_sum, disim_sum  (+ finish ticket).
// Zero at module load; the LAST block of each launch resets them after
// computing the loss, so every graph replay starts from zero.
__device__ double g_acc[4];
__device__ int g_done;

__global__ void __launch_bounds__(BLOCK_THREADS)
lp_fused_kernel(const void* __restrict__ edges,
                const float* __restrict__ probas,
                const float* __restrict__ feats,
                float* __restrict__ out,
                int n_edges, int n_nodes, int chunk, int nblocks) {
    __shared__ int2 s_buf[NWARPS][RING];
    __shared__ int s_is64;
    __shared__ float s_red[4][NWARPS];
    __shared__ int s_last;

    int tid = threadIdx.x;
    int lane = tid & 31;
    int w = tid >> 5;
    int g = lane >> 3;        // dense phase: group 0..3 (one edge each)
    int q = lane & 7;         // float4 chunk index within group

    if (tid == 0) {
        // int64 edges: odd 32-bit words (high halves of idx < 2^31) are zero.
        const int4* hw = reinterpret_cast<const int4*>(edges);
        int4 a = __ldg(&hw[0]);
        int4 b = __ldg(&hw[1]);
        s_is64 = ((a.y | a.w | b.y | b.w) == 0) ? 1 : 0;
    }
    __syncthreads();
    const int is64 = s_is64;

    const longlong2* e64 = reinterpret_cast<const longlong2*>(edges);
    const int2* e32 = reinterpret_cast<const int2*>(edges);
    const char* fbase = reinterpret_cast<const char*>(feats);
    // Row i starts at byte i << 8 (64 floats * 4B = 256B per row).
    const unsigned qoff1 = (unsigned)q * 16u;        // bytes 0..112
    const unsigned qoff2 = qoff1 + 128u;             // bytes 128..240
    const unsigned nmax = (unsigned)n_nodes - 1u;    // clamp bound

    // Per-warp contiguous range: 4 batched sub-tiles of 32 per macro-iter.
    int beg = blockIdx.x * chunk;
    int end = min(beg + chunk, n_edges);
    int ws = (chunk + NWARPS - 1) / NWARPS;
    int wbeg = beg + w * ws;
    int wend = min(wbeg + ws, end);

    float n_sim = 0.f, n_dis = 0.f, s_sim = 0.f, s_dis = 0.f;
    int wcnt = 0;   // unprocessed ring entries (warp-uniform)
    int head = 0;   // ring read position (warp-uniform)

    auto ld4 = [&](unsigned byte_off) {
        return __ldg(reinterpret_cast<const float4*>(fbase + byte_off));
    };

    // Dense-process 32 buffered masked edges: pairs of 4-edge passes with all
    // 8 LDG.128 issued before any FMA; two shfl chains interleaved.
    auto flush32 = [&]() {
        __syncwarp();
#pragma unroll
        for (int t = 0; t < 8; t += 2) {
            int2 e0 = s_buf[w][(head + t * 4 + g) & (RING - 1)];
            int2 e1 = s_buf[w][(head + (t + 1) * 4 + g) & (RING - 1)];
            unsigned o0i = (unsigned)(e0.x & 0x7FFFFFFF) << 8;
            unsigned o0j = (unsigned)e0.y << 8;
            unsigned o1i = (unsigned)(e1.x & 0x7FFFFFFF) << 8;
            unsigned o1j = (unsigned)e1.y << 8;
            float4 a0 = ld4(o0i + qoff1);
            float4 c0 = ld4(o0i + qoff2);
            float4 b0 = ld4(o0j + qoff1);
            float4 d0 = ld4(o0j + qoff2);
            float4 a1 = ld4(o1i + qoff1);
            float4 c1 = ld4(o1i + qoff2);
            float4 b1 = ld4(o1j + qoff1);
            float4 d1 = ld4(o1j + qoff2);

            float x, y, z, v;
            x = a0.x - b0.x; y = a0.y - b0.y; z = a0.z - b0.z; v = a0.w - b0.w;
            float s0 = fmaf(x, x, fmaf(y, y, fmaf(z, z, v * v)));
            x = c0.x - d0.x; y = c0.y - d0.y; z = c0.z - d0.z; v = c0.w - d0.w;
            s0 += fmaf(x, x, fmaf(y, y, fmaf(z, z, v * v)));
            x = a1.x - b1.x; y = a1.y - b1.y; z = a1.z - b1.z; v = a1.w - b1.w;
            float s1 = fmaf(x, x, fmaf(y, y, fmaf(z, z, v * v)));
            x = c1.x - d1.x; y = c1.y - d1.y; z = c1.z - d1.z; v = c1.w - d1.w;
            s1 += fmaf(x, x, fmaf(y, y, fmaf(z, z, v * v)));

            s0 += __shfl_xor_sync(0xFFFFFFFFu, s0, 1);
            s1 += __shfl_xor_sync(0xFFFFFFFFu, s1, 1);
            s0 += __shfl_xor_sync(0xFFFFFFFFu, s0, 2);
            s1 += __shfl_xor_sync(0xFFFFFFFFu, s1, 2);
            s0 += __shfl_xor_sync(0xFFFFFFFFu, s0, 4);
            s1 += __shfl_xor_sync(0xFFFFFFFFu, s1, 4);

            if (q == 0) {
                float d = sqrtf(s0);
                if (e0.x < 0) s_sim += fminf(d, 100.f);
                else          s_dis += -fmaxf(log1pf(-expf(-d)), -100.f);
                d = sqrtf(s1);
                if (e1.x < 0) s_sim += fminf(d, 100.f);
                else          s_dis += -fmaxf(log1pf(-expf(-d)), -100.f);
            }
        }
        head = (head + 32) & (RING - 1);
        wcnt -= 32;
    };

    // Scan: 128 edges per warp-iter, all loads batched for MLP.
    // Index handling diet (R16): no range-check/select chain — indices are
    // clamped to [0, n_nodes-1] with one umin each (pure memory safety;
    // clamped values only feed gathers), and only e<wend gates the mask.
    for (int mb = wbeg; mb < wend; mb += 128) {   // warp-uniform bound
        int ei[4], ej[4];
        bool val[4];
#pragma unroll
        for (int t = 0; t < 4; t++) {
            int e = mb + t * 32 + lane;
            val[t] = e < wend;
            int i = 0, j = 0;
            if (val[t]) {
                if (is64) { longlong2 ij = e64[e]; i = (int)ij.x; j = (int)ij.y; }
                else      { int2 ij = e32[e];      i = ij.x;      j = ij.y; }
            }
            ei[t] = (int)min((unsigned)i, nmax);   // clamp: memory safety only
            ej[t] = (int)min((unsigned)j, nmax);
        }
        float pi[4], pj[4];
#pragma unroll
        for (int t = 0; t < 4; t++) {
            pi[t] = __ldg(&probas[ei[t]]);
            pj[t] = __ldg(&probas[ej[t]]);
        }
#pragma unroll
        for (int t = 0; t < 4; t++) {
            bool ms = val[t] && (pi[t] >= THR_HI) && (pj[t] >= THR_HI);
            bool md = val[t] &&
                      (((pi[t] >= THR_HI) && (pj[t] < THR_LO)) ||
                       ((pj[t] >= THR_HI) && (pi[t] < THR_LO)));
            n_sim += ms ? 1.f : 0.f;
            n_dis += md ? 1.f : 0.f;

            unsigned bal = __ballot_sync(0xFFFFFFFFu, ms | md);
            int rank = __popc(bal & ((1u << lane) - 1u));
            if (ms | md)
                s_buf[w][(head + wcnt + rank) & (RING - 1)] =
                    make_int2(ei[t] | (ms ? (int)0x80000000 : 0), ej[t]);
            wcnt += __popc(bal);                  // warp-uniform
            if (wcnt >= 32) flush32();            // warp-uniform condition
        }
    }

    // Tail (< 32 entries): warp-uniform bound, predicated work, all lanes
    // run the shfls (R4 lesson).
    if (wcnt > 0) {
        __syncwarp();
        for (int t = 0; t < wcnt; t += 4) {
            int it = t + g;
            bool act = it < wcnt;
            int2 ed = act ? s_buf[w][(head + it) & (RING - 1)]
                          : make_int2(0, 0);
            bool ms = ed.x < 0;
            unsigned oi = (unsigned)(ed.x & 0x7FFFFFFF) << 8;
            unsigned oj = (unsigned)ed.y << 8;
            float4 a1 = make_float4(0.f, 0.f, 0.f, 0.f);
            float4 a2 = a1, b1 = a1, b2 = a1;
            if (act) {
                a1 = ld4(oi + qoff1);  a2 = ld4(oi + qoff2);
                b1 = ld4(oj + qoff1);  b2 = ld4(oj + qoff2);
            }
            float dx = a1.x - b1.x, dy = a1.y - b1.y;
            float dz = a1.z - b1.z, dw = a1.w - b1.w;
            float s = fmaf(dx, dx, fmaf(dy, dy, fmaf(dz, dz, dw * dw)));
            dx = a2.x - b2.x; dy = a2.y - b2.y;
            dz = a2.z - b2.z; dw = a2.w - b2.w;
            s += fmaf(dx, dx, fmaf(dy, dy, fmaf(dz, dz, dw * dw)));
            s += __shfl_xor_sync(0xFFFFFFFFu, s, 1);
            s += __shfl_xor_sync(0xFFFFFFFFu, s, 2);
            s += __shfl_xor_sync(0xFFFFFFFFu, s, 4);
            if (act && q == 0) {
                float d = sqrtf(s);
                if (ms) s_sim += fminf(d, 100.f);
                else    s_dis += -fmaxf(log1pf(-expf(-d)), -100.f);
            }
        }
    }

    // Block reduce 4 partials
#pragma unroll
    for (int off = 16; off > 0; off >>= 1) {
        n_sim += __shfl_down_sync(0xFFFFFFFFu, n_sim, off);
        n_dis += __shfl_down_sync(0xFFFFFFFFu, n_dis, off);
        s_sim += __shfl_down_sync(0xFFFFFFFFu, s_sim, off);
        s_dis += __shfl_down_sync(0xFFFFFFFFu, s_dis, off);
    }
    if (lane == 0) {
        s_red[0][w] = n_sim; s_red[1][w] = n_dis;
        s_red[2][w] = s_sim; s_red[3][w] = s_dis;
    }
    __syncthreads();

    if (tid == 0) {
        float a0 = 0.f, a1 = 0.f, a2 = 0.f, a3 = 0.f;
#pragma unroll
        for (int k = 0; k < NWARPS; k++) {
            a0 += s_red[0][k]; a1 += s_red[1][k];
            a2 += s_red[2][k]; a3 += s_red[3][k];
        }
        atomicAdd(&g_acc[0], (double)a0);
        atomicAdd(&g_acc[1], (double)a1);
        atomicAdd(&g_acc[2], (double)a2);
        atomicAdd(&g_acc[3], (double)a3);
        __threadfence();
        int ticket = atomicAdd(&g_done, 1);
        s_last = (ticket == nblocks - 1);
    }
    __syncthreads();

    // Last block computes the loss, then resets state for the next replay.
    if (s_last && tid == 0) {
        double ns = g_acc[0], nd = g_acc[1], ss = g_acc[2], ds = g_acc[3];
        double total = ns + nd;
        double loss = (ss * (nd / total) + ds * (ns / total)) / total;
        out[0] = (float)loss;
        g_acc[0] = 0.0; g_acc[1] = 0.0; g_acc[2] = 0.0; g_acc[3] = 0.0;
        g_done = 0;
    }
}

extern "C" void kernel_launch(void* const* d_in, const int* in_sizes, int n_in,
                              void* d_out, int out_size) {
    // Identify inputs by element count (robust to metadata ordering):
    //   probas: n_nodes (smallest), feats: n_nodes*64, edges: the rest.
    int idx_e = 0, idx_p = 1, idx_f = 2;
    if (n_in == 3) {
        int smallest = 0;
        for (int k = 1; k < 3; k++)
            if (in_sizes[k] < in_sizes[smallest]) smallest = k;
        int pf = -1, ee = -1;
        for (int k = 0; k < 3; k++) {
            if (k == smallest) continue;
            if (in_sizes[k] == in_sizes[smallest] * 64) pf = k;
            else ee = k;
        }
        if (pf >= 0 && ee >= 0) { idx_p = smallest; idx_f = pf; idx_e = ee; }
    }

    const void* edges = d_in[idx_e];
    const float* probas = (const float*)d_in[idx_p];
    const float* feats = (const float*)d_in[idx_f];
    float* out = (float*)d_out;

    int n_edges = in_sizes[idx_e] / 2;
    int n_nodes = in_sizes[idx_p];
    int chunk = (n_edges + GRID_BLOCKS - 1) / GRID_BLOCKS;

    lp_fused_kernel<<<GRID_BLOCKS, BLOCK_THREADS>>>(
        edges, probas, feats, out, n_edges, n_nodes, chunk, GRID_BLOCKS);
}